// round 11
// baseline (speedup 1.0000x reference)
#include <cuda_runtime.h>
#include <cuda_bf16.h>
#include <math.h>

#define B_     2
#define C_     128
#define HW_    36864
#define N_     73728
#define E_     4
#define HID_   340
#define HIDP_  384
#define NCHW_  9437184
#define NTILE_ (N_ / 64)

typedef unsigned long long u64;
typedef unsigned int u32;

__device__ __forceinline__ float gelu_exact(float v) {
    return 0.5f * v * (1.0f + erff(v * 0.70710678118654752440f));
}
// pack {lo, hi} floats -> bf16x2 in one u32 (lo in low 16 bits)
__device__ __forceinline__ u32 pkbf(float lo, float hi) {
    u32 d; asm("cvt.rn.bf16x2.f32 %0, %1, %2;" : "=r"(d) : "f"(hi), "f"(lo)); return d;
}
__device__ __forceinline__ void mma_bf16(float& c0, float& c1, float& c2, float& c3,
                                         u32 a0, u32 a1, u32 a2, u32 a3, u32 b0, u32 b1) {
    asm("mma.sync.aligned.m16n8k16.row.col.f32.bf16.bf16.f32 "
        "{%0,%1,%2,%3}, {%4,%5,%6,%7}, {%8,%9}, {%0,%1,%2,%3};"
        : "+f"(c0), "+f"(c1), "+f"(c2), "+f"(c3)
        : "r"(a0), "r"(a1), "r"(a2), "r"(a3), "r"(b0), "r"(b1));
}

// ----------------------------- device scratch -----------------------------
__device__ float g_part[1024];                 // partial row sums (mean stage 1)
__device__ float g_emb[B_ * C_];
__device__ float g_WbT[B_ * C_ * C_];          // [b][c][o]
__device__ float g_lpart[NTILE_ * 8];          // per-CTA loss partials [imp0..3, load0..3]
// packed bf16 weights in m16n8k16 B-fragment order
__device__ u32   g_w1k[98304];                 // [e][24 pr][8 kt][32 lane][4]
__device__ u32   g_w2k[98304];                 // [e][8 pr][24 kt][32 lane][4]
__device__ u32   g_wck[16384];                 // conv: [b][8 pr][8 kt][32 lane][4]
__device__ float g_b1p[E_ * HIDP_];            // padded b1

// ---------------------- K1: channel means (stage 1) ----------------------
__global__ void k_mean1(const float* __restrict__ x) {
    int part = blockIdx.x;                  // row*4 + q
    int row = part >> 2, q = part & 3;
    int t = threadIdx.x;
    const float4* xr = (const float4*)(x + (size_t)row * HW_) + q * 2304;
    float s = 0.f;
    #pragma unroll
    for (int i = 0; i < 9; i++) {
        float4 v = xr[t + i * 256];
        s += (v.x + v.y) + (v.z + v.w);
    }
    __shared__ float sm[256];
    sm[t] = s; __syncthreads();
    for (int o = 128; o > 0; o >>= 1) {
        if (t < o) sm[t] += sm[t + o];
        __syncthreads();
    }
    if (t == 0) g_part[part] = sm[0];
}

// ------ K2: mean reduce + prompt softmax + fold conv W (256 threads) ------
__global__ void k_prep(const float* __restrict__ prompt, const float* __restrict__ w_lin,
                       const float* __restrict__ b_lin, const float* __restrict__ w_conv) {
    int t = threadIdx.x;
    __shared__ float s_l[B_ * 5], s_pw[B_ * 5], s_sp[B_ * C_];
    {   // finish channel means
        float4 p = *(const float4*)(g_part + t * 4);
        g_emb[t] = ((p.x + p.y) + (p.z + p.w)) * (1.0f / (float)HW_);
    }
    __syncthreads();
    if (t < B_ * 5) {
        int b = t / 5, p = t % 5;
        float a = b_lin[p];
        for (int c = 0; c < C_; c++) a += g_emb[b * C_ + c] * w_lin[p * C_ + c];
        s_l[t] = a;
    }
    __syncthreads();
    if (t < B_) {
        float m = s_l[t * 5];
        for (int p = 1; p < 5; p++) m = fmaxf(m, s_l[t * 5 + p]);
        float e[5]; float den = 0.f;
        for (int p = 0; p < 5; p++) { e[p] = expf(s_l[t * 5 + p] - m); den += e[p]; }
        for (int p = 0; p < 5; p++) s_pw[t * 5 + p] = e[p] / den;
    }
    __syncthreads();
    {
        int b = t >> 7, c = t & 127;
        float a = 0.f;
        for (int p = 0; p < 5; p++) a += s_pw[b * 5 + p] * prompt[p * C_ + c];
        s_sp[t] = a;
    }
    __syncthreads();
    for (int i = t; i < B_ * C_ * C_; i += 256) {
        int b = i >> 14; int rem = i & 16383; int c = rem >> 7; int o = rem & 127;
        g_WbT[i] = w_conv[o * C_ + c] * s_sp[b * C_ + c];
    }
}

// ----------------- K2b: pack weights to bf16 fragments -----------------
__global__ void k_pack(const float* __restrict__ w1, const float* __restrict__ b1,
                       const float* __restrict__ w2) {
    int i = blockIdx.x * 256 + threadIdx.x;
    if (i < 98304) {                 // w1k: n8 pairs over HIDP, k over C
        int r = i & 3, lane = (i >> 2) & 31, kt = (i >> 7) & 7;
        int pe = i >> 10; int pr = pe % 24; int e = pe / 24;
        int n = (pr * 2 + (r >> 1)) * 8 + (lane >> 2);
        int k = kt * 16 + (lane & 3) * 2 + (r & 1) * 8;
        float v0 = 0.f, v1 = 0.f;
        if (n < HID_) {
            v0 = w1[((size_t)(e * C_ + k)) * HID_ + n];
            v1 = w1[((size_t)(e * C_ + k + 1)) * HID_ + n];
        }
        g_w1k[i] = pkbf(v0, v1);
    } else if (i < 196608) {         // w2k: n8 pairs over C, k over HIDP
        int j = i - 98304;
        int r = j & 3, lane = (j >> 2) & 31;
        int rest = j >> 7; int kt = rest % 24; int pe = rest / 24;
        int pr = pe & 7; int e = pe >> 3;
        int n = (pr * 2 + (r >> 1)) * 8 + (lane >> 2);
        int k = kt * 16 + (lane & 3) * 2 + (r & 1) * 8;
        float v0 = (k < HID_)     ? w2[((size_t)(e * HID_ + k)) * C_ + n]     : 0.f;
        float v1 = (k + 1 < HID_) ? w2[((size_t)(e * HID_ + k + 1)) * C_ + n] : 0.f;
        g_w2k[j] = pkbf(v0, v1);
    } else if (i < 196608 + E_ * HIDP_) {
        int l = i - 196608; int e = l / HIDP_, n = l % HIDP_;
        g_b1p[l] = (n < HID_) ? b1[e * HID_ + n] : 0.f;
    } else if (i < 196608 + E_ * HIDP_ + 16384) {   // conv weights (needs g_WbT)
        int j = i - (196608 + E_ * HIDP_);
        int r = j & 3, lane = (j >> 2) & 31, kt = (j >> 7) & 7;
        int pe = j >> 10; int pr = pe & 7; int b = pe >> 3;
        int n = (pr * 2 + (r >> 1)) * 8 + (lane >> 2);
        int k = kt * 16 + (lane & 3) * 2 + (r & 1) * 8;
        float v0 = g_WbT[b * 16384 + k * 128 + n];
        float v1 = g_WbT[b * 16384 + (k + 1) * 128 + n];
        g_wck[j] = pkbf(v0, v1);
    }
}

// ============ K3: FUSED conv + gating + dense MoE + residual ============
// smem words: s_x[64*130 f] | s_wg[512 f] | s_lg[256 f] | s_g[256 f] |
//             s_a[4096 u32] | s_h[12288 u32]
#define CVP    130
#define MX_WG  8320
#define MX_LG  8832
#define MX_G   9088
#define MX_A   9344
#define MX_H   13440
#define MX_TOT 25728
#define MX_BYTES (MX_TOT * 4)

__global__ void __launch_bounds__(256, 2) k_moe(const float* __restrict__ x,
                                                const float* __restrict__ w_gate,
                                                const float* __restrict__ b2,
                                                float* __restrict__ dout) {
    extern __shared__ __align__(16) u32 ms[];
    float* s_x  = (float*)ms;                 // [tok][CVP], becomes y-accumulator
    float* s_wg = (float*)(ms + MX_WG);
    float* s_lg = (float*)(ms + MX_LG);
    float* s_g  = (float*)(ms + MX_G);        // dense gates [tok][4]
    u32*   s_a  = ms + MX_A;                  // conv-in frags, then ty frags
    u32*   s_h  = ms + MX_H;                  // hidden frags (per expert)
    int t = threadIdx.x;
    int n0 = blockIdx.x * 64;
    int b = n0 / HW_; int hw0 = n0 % HW_;
    const float* xb = x + (size_t)b * C_ * HW_ + hw0;
    s_wg[t] = w_gate[t]; s_wg[t + 256] = w_gate[t + 256];
    s_g[t] = 0.f;
    #pragma unroll
    for (int i = 0; i < 32; i++) {
        int idx = t + i * 256; int c = idx >> 6, tk = idx & 63;
        s_x[tk * CVP + c] = xb[(size_t)c * HW_ + tk];
    }
    __syncthreads();
    {   // gating logits (fp32 exact): thread = (expert, token), 4-way ILP
        int e = t >> 6, tk = t & 63;
        const float* xr = s_x + tk * CVP;
        float a0 = 0.f, a1 = 0.f, a2 = 0.f, a3 = 0.f;
        #pragma unroll
        for (int c = 0; c < C_; c += 4) {
            a0 = fmaf(xr[c],     s_wg[c * 4 + e],       a0);
            a1 = fmaf(xr[c + 1], s_wg[(c + 1) * 4 + e], a1);
            a2 = fmaf(xr[c + 2], s_wg[(c + 2) * 4 + e], a2);
            a3 = fmaf(xr[c + 3], s_wg[(c + 3) * 4 + e], a3);
        }
        s_lg[tk * 4 + e] = (a0 + a1) + (a2 + a3);
    }
    // build conv-input bf16 A-fragments
    #pragma unroll
    for (int i = 0; i < 16; i++) {
        int idx = t + i * 256;           // 64 tokens x 64 col-pairs
        int m = idx >> 6, cp = idx & 63, c = cp * 2;
        float2 v = *(const float2*)(s_x + m * CVP + c);
        int mt = m >> 4, mr = m & 15, gg = mr & 7, hi = mr >> 3;
        int kt = c >> 4, ko = c & 15, half = ko >> 3, tg = (ko & 7) >> 1;
        int lane = gg * 4 + tg, reg = half * 2 + hi;
        s_a[((mt * 8 + kt) * 32 + lane) * 4 + reg] = pkbf(v.x, v.y);
    }
    __syncthreads();
    if (t < 64) {       // top-2 + softmax -> dense gates
        float l[4];
        #pragma unroll
        for (int e = 0; e < 4; e++) l[e] = s_lg[t * 4 + e];
        int e0 = 0; float m0 = l[0];
        #pragma unroll
        for (int e = 1; e < 4; e++) if (l[e] > m0) { m0 = l[e]; e0 = e; }
        int e1 = (e0 == 0) ? 1 : 0; float m1 = l[e1];
        #pragma unroll
        for (int e = 0; e < 4; e++) if (e != e0 && l[e] > m1) { m1 = l[e]; e1 = e; }
        float ex = expf(m1 - m0);
        float g0 = 1.0f / (1.0f + ex);
        s_g[t * 4 + e0] = g0;
        s_g[t * 4 + e1] = ex * g0;
    }
    int warp = t >> 5, lane = t & 31, gg = lane >> 2, tg = lane & 3;
    int mt = warp & 3, nh = warp >> 2;
    // ---- conv HMMA: M=64, N half=64 (nh), K=128 ----
    {
        float acc[8][4];
        #pragma unroll
        for (int nt = 0; nt < 8; nt++)
            #pragma unroll
            for (int r = 0; r < 4; r++) acc[nt][r] = 0.f;
        const u32* wbase = g_wck + (b * 8 + nh * 4) * 1024 + lane * 4;
        #pragma unroll
        for (int kt = 0; kt < 8; kt++) {
            uint4 A = *(const uint4*)(s_a + ((mt * 8 + kt) * 32 + lane) * 4);
            #pragma unroll
            for (int j = 0; j < 4; j++) {
                uint4 Bv = *(const uint4*)(wbase + j * 1024 + kt * 128);
                mma_bf16(acc[2*j][0],   acc[2*j][1],   acc[2*j][2],   acc[2*j][3],
                         A.x, A.y, A.z, A.w, Bv.x, Bv.y);
                mma_bf16(acc[2*j+1][0], acc[2*j+1][1], acc[2*j+1][2], acc[2*j+1][3],
                         A.x, A.y, A.z, A.w, Bv.z, Bv.w);
            }
        }
        __syncthreads();   // all warps done reading conv-input frags
        // conv accum frag pair == fc1 A-frag: overwrite s_a with ty frags
        #pragma unroll
        for (int j = 0; j < 4; j++) {
            int ktg = nh * 4 + j;
            u32 r0 = pkbf(acc[2*j][0],   acc[2*j][1]);
            u32 r1 = pkbf(acc[2*j][2],   acc[2*j][3]);
            u32 r2 = pkbf(acc[2*j+1][0], acc[2*j+1][1]);
            u32 r3 = pkbf(acc[2*j+1][2], acc[2*j+1][3]);
            *(uint4*)(s_a + ((mt * 8 + ktg) * 32 + lane) * 4) = make_uint4(r0, r1, r2, r3);
        }
    }
    __syncthreads();

    // ---- dense expert loop: y (in s_x) += gate_e * (fc2(gelu(fc1)) + b2) ----
    for (int e = 0; e < E_; e++) {
        // fc1: two passes of 12 n8-tiles; write gelu'd frags to s_h
        for (int p = 0; p < 2; p++) {
            float acc[12][4];
            #pragma unroll
            for (int j2 = 0; j2 < 12; j2++) {
                int nt = nh * 24 + p * 12 + j2;
                float2 bv = *(const float2*)(g_b1p + e * HIDP_ + nt * 8 + tg * 2);
                acc[j2][0] = bv.x; acc[j2][1] = bv.y; acc[j2][2] = bv.x; acc[j2][3] = bv.y;
            }
            const u32* wbase = g_w1k + (e * 24 + nh * 12 + p * 6) * 1024 + lane * 4;
            #pragma unroll
            for (int kt = 0; kt < 8; kt++) {
                uint4 A = *(const uint4*)(s_a + ((mt * 8 + kt) * 32 + lane) * 4);
                #pragma unroll
                for (int j = 0; j < 6; j++) {
                    uint4 Bv = *(const uint4*)(wbase + j * 1024 + kt * 128);
                    mma_bf16(acc[2*j][0],   acc[2*j][1],   acc[2*j][2],   acc[2*j][3],
                             A.x, A.y, A.z, A.w, Bv.x, Bv.y);
                    mma_bf16(acc[2*j+1][0], acc[2*j+1][1], acc[2*j+1][2], acc[2*j+1][3],
                             A.x, A.y, A.z, A.w, Bv.z, Bv.w);
                }
            }
            #pragma unroll
            for (int j = 0; j < 6; j++) {
                int ktg = nh * 12 + p * 6 + j;
                u32 r0 = pkbf(gelu_exact(acc[2*j][0]),   gelu_exact(acc[2*j][1]));
                u32 r1 = pkbf(gelu_exact(acc[2*j][2]),   gelu_exact(acc[2*j][3]));
                u32 r2 = pkbf(gelu_exact(acc[2*j+1][0]), gelu_exact(acc[2*j+1][1]));
                u32 r3 = pkbf(gelu_exact(acc[2*j+1][2]), gelu_exact(acc[2*j+1][3]));
                *(uint4*)(s_h + ((mt * 24 + ktg) * 32 + lane) * 4) = make_uint4(r0, r1, r2, r3);
            }
        }
        __syncthreads();
        // fc2: M=64, N half=64, K=384
        float out[8][4];
        #pragma unroll
        for (int nt = 0; nt < 8; nt++) {
            float2 bv = *(const float2*)(b2 + e * C_ + (nh * 8 + nt) * 8 + tg * 2);
            out[nt][0] = bv.x; out[nt][1] = bv.y; out[nt][2] = bv.x; out[nt][3] = bv.y;
        }
        const u32* w2base = g_w2k + (e * 8 + nh * 4) * 3072 + lane * 4;
        #pragma unroll 2
        for (int kt = 0; kt < 24; kt++) {
            uint4 A = *(const uint4*)(s_h + ((mt * 24 + kt) * 32 + lane) * 4);
            #pragma unroll
            for (int j = 0; j < 4; j++) {
                uint4 Bv = *(const uint4*)(w2base + j * 3072 + kt * 128);
                mma_bf16(out[2*j][0],   out[2*j][1],   out[2*j][2],   out[2*j][3],
                         A.x, A.y, A.z, A.w, Bv.x, Bv.y);
                mma_bf16(out[2*j+1][0], out[2*j+1][1], out[2*j+1][2], out[2*j+1][3],
                         A.x, A.y, A.z, A.w, Bv.z, Bv.w);
            }
        }
        // gated accumulate into s_x (thread-exclusive cells)
        int m0 = mt * 16 + gg, m1 = m0 + 8;
        float gg0 = s_g[m0 * 4 + e], gg1 = s_g[m1 * 4 + e];
        #pragma unroll
        for (int nt = 0; nt < 8; nt++) {
            int c = (nh * 8 + nt) * 8 + tg * 2;
            s_x[m0 * CVP + c]     += gg0 * out[nt][0];
            s_x[m0 * CVP + c + 1] += gg0 * out[nt][1];
            s_x[m1 * CVP + c]     += gg1 * out[nt][2];
            s_x[m1 * CVP + c + 1] += gg1 * out[nt][3];
        }
        __syncthreads();   // s_h reuse / final s_x complete
    }
    // loss partials (deterministic per-CTA)
    if (t < 8) {
        int e = t & 3; int isLoad = t >> 2;
        float s = 0.f;
        #pragma unroll 4
        for (int m = 0; m < 64; m++) {
            float g = s_g[m * 4 + e];
            s += isLoad ? (g > 0.f ? 1.f : 0.f) : g;
        }
        g_lpart[blockIdx.x * 8 + t] = s;
    }
    // NCHW write: y = x + sum(gate*o) already in s_x
    size_t base = (size_t)b * C_ * HW_ + hw0;
    #pragma unroll
    for (int i = 0; i < 16; i++) {       // 128 c x 32 float2
        int lin = t + i * 256; int c = lin >> 5, k = lin & 31;
        float2 v = make_float2(s_x[(2 * k) * CVP + c], s_x[(2 * k + 1) * CVP + c]);
        *(float2*)(dout + base + (size_t)c * HW_ + 2 * k) = v;
    }
}

// ------------------------------- K4: aux loss -------------------------------
__global__ void k_loss(float* __restrict__ dout, int has_loss) {
    int t = threadIdx.x; int w = t >> 5, lane = t & 31;
    __shared__ float red[8];
    if (w < 8) {
        float s = 0.f;
        for (int i = lane; i < NTILE_; i += 32) s += g_lpart[i * 8 + w];
        #pragma unroll
        for (int o = 16; o > 0; o >>= 1) s += __shfl_xor_sync(0xffffffff, s, o);
        if (lane == 0) red[w] = s;
    }
    __syncthreads();
    if (t == 0 && has_loss) {
        float mi = 0.f, ml = 0.f;
        for (int k = 0; k < E_; k++) { mi += red[k]; ml += red[4 + k]; }
        mi *= 0.25f; ml *= 0.25f;
        float vi = 0.f, vl = 0.f;
        for (int k = 0; k < E_; k++) {
            float di = red[k] - mi, dl = red[4 + k] - ml;
            vi += di * di; vl += dl * dl;
        }
        vi *= 0.25f; vl *= 0.25f;
        float loss = 1e-2f * (vi / (mi * mi + 1e-10f) + vl / (ml * ml + 1e-10f));
        dout[NCHW_] = loss;
    }
}

// --------------------------------- launcher ---------------------------------
extern "C" void kernel_launch(void* const* d_in, const int* in_sizes, int n_in,
                              void* d_out, int out_size) {
    const float* x      = (const float*)d_in[0];
    const float* prompt = (const float*)d_in[1];
    const float* w_lin  = (const float*)d_in[2];
    const float* b_lin  = (const float*)d_in[3];
    const float* w_conv = (const float*)d_in[4];
    const float* w_gate = (const float*)d_in[5];
    const float* w1     = (const float*)d_in[6];
    const float* b1     = (const float*)d_in[7];
    const float* w2     = (const float*)d_in[8];
    const float* b2     = (const float*)d_in[9];
    float* out = (float*)d_out;

    cudaFuncSetAttribute(k_moe, cudaFuncAttributeMaxDynamicSharedMemorySize, MX_BYTES);

    k_mean1<<<1024, 256>>>(x);
    k_prep<<<1, 256>>>(prompt, w_lin, b_lin, w_conv);
    int packn = 196608 + E_ * HIDP_ + 16384;
    k_pack<<<(packn + 255) / 256, 256>>>(w1, b1, w2);
    k_moe<<<NTILE_, 256, MX_BYTES>>>(x, w_gate, b2, out);
    k_loss<<<1, 256>>>(out, (out_size > NCHW_) ? 1 : 0);
}

// round 13
// speedup vs baseline: 1.0373x; 1.0373x over previous
#include <cuda_runtime.h>
#include <cuda_bf16.h>
#include <math.h>

#define B_     2
#define C_     128
#define HW_    36864
#define N_     73728
#define E_     4
#define HID_   340
#define NCHW_  9437184

typedef unsigned long long u64;
typedef unsigned int u32;

__device__ __forceinline__ float gelu_exact(float v) {
    return 0.5f * v * (1.0f + erff(v * 0.70710678118654752440f));
}
__device__ __forceinline__ u32 pkbf(float lo, float hi) {
    u32 d; asm("cvt.rn.bf16x2.f32 %0, %1, %2;" : "=r"(d) : "f"(hi), "f"(lo)); return d;
}
__device__ __forceinline__ float2 upbf(u32 v) {
    __nv_bfloat162 b = *(__nv_bfloat162*)&v;
    return __bfloat1622float2(b);
}
__device__ __forceinline__ void mma_bf16(float* c,
                                         u32 a0, u32 a1, u32 a2, u32 a3, u32 b0, u32 b1) {
    asm("mma.sync.aligned.m16n8k16.row.col.f32.bf16.bf16.f32 "
        "{%0,%1,%2,%3}, {%4,%5,%6,%7}, {%8,%9}, {%0,%1,%2,%3};"
        : "+f"(c[0]), "+f"(c[1]), "+f"(c[2]), "+f"(c[3])
        : "r"(a0), "r"(a1), "r"(a2), "r"(a3), "r"(b0), "r"(b1));
}

// ----------------------------- device scratch -----------------------------
__device__ float g_part[1024];
__device__ float g_emb[B_ * C_];
__device__ float g_WbT[B_ * C_ * C_];           // [b][c][o]
__device__ u32   g_tyb[(size_t)N_ * 64];        // conv-out tokens, bf16x2 [n][cpair]
__device__ int   g_cnt[E_];
__device__ int   g_tok[E_ * N_];
__device__ float g_gate[E_ * N_];
__device__ int   g_slot[N_ * 2];
__device__ u32   g_obufh[(size_t)E_ * N_ * 64]; // gated expert outputs, bf16x2
__device__ u32   g_wck[16384];                  // conv weights, frag order
__device__ u32   g_w1k[98304];                  // [e][24 pr][8 kt][32 lane][4]
__device__ u32   g_w2k[98304];                  // [e][3 ch][8 pr][8 kc][32 lane][4]

// ---------------------- K1: channel means (stage 1) ----------------------
__global__ void k_mean1(const float* __restrict__ x) {
    int part = blockIdx.x;
    int row = part >> 2, q = part & 3;
    int t = threadIdx.x;
    const float4* xr = (const float4*)(x + (size_t)row * HW_) + q * 2304;
    float s = 0.f;
    #pragma unroll
    for (int i = 0; i < 9; i++) {
        float4 v = xr[t + i * 256];
        s += (v.x + v.y) + (v.z + v.w);
    }
    __shared__ float sm[256];
    sm[t] = s; __syncthreads();
    for (int o = 128; o > 0; o >>= 1) {
        if (t < o) sm[t] += sm[t + o];
        __syncthreads();
    }
    if (t == 0) g_part[part] = sm[0];
}

// ------ K2: mean reduce + prompt softmax + fold conv W ------
__global__ void k_prep(const float* __restrict__ prompt, const float* __restrict__ w_lin,
                       const float* __restrict__ b_lin, const float* __restrict__ w_conv) {
    int t = threadIdx.x;
    __shared__ float s_l[B_ * 5], s_pw[B_ * 5], s_sp[B_ * C_];
    {
        float4 p = *(const float4*)(g_part + t * 4);
        g_emb[t] = ((p.x + p.y) + (p.z + p.w)) * (1.0f / (float)HW_);
    }
    if (t < E_) g_cnt[t] = 0;
    __syncthreads();
    if (t < B_ * 5) {
        int b = t / 5, p = t % 5;
        float a = b_lin[p];
        for (int c = 0; c < C_; c++) a += g_emb[b * C_ + c] * w_lin[p * C_ + c];
        s_l[t] = a;
    }
    __syncthreads();
    if (t < B_) {
        float m = s_l[t * 5];
        for (int p = 1; p < 5; p++) m = fmaxf(m, s_l[t * 5 + p]);
        float e[5]; float den = 0.f;
        for (int p = 0; p < 5; p++) { e[p] = expf(s_l[t * 5 + p] - m); den += e[p]; }
        for (int p = 0; p < 5; p++) s_pw[t * 5 + p] = e[p] / den;
    }
    __syncthreads();
    {
        int b = t >> 7, c = t & 127;
        float a = 0.f;
        for (int p = 0; p < 5; p++) a += s_pw[b * 5 + p] * prompt[p * C_ + c];
        s_sp[t] = a;
    }
    __syncthreads();
    for (int i = t; i < B_ * C_ * C_; i += 256) {
        int b = i >> 14; int rem = i & 16383; int c = rem >> 7; int o = rem & 127;
        g_WbT[i] = w_conv[o * C_ + c] * s_sp[b * C_ + c];
    }
}

// ----------------- K2b: pack weights to bf16 fragment images -----------------
__global__ void k_pack(const float* __restrict__ w1, const float* __restrict__ w2) {
    int i = blockIdx.x * 256 + threadIdx.x;
    if (i < 98304) {                 // w1k: [e][24 pr over hid][8 kt over C]
        int r = i & 3, lane = (i >> 2) & 31, kt = (i >> 7) & 7;
        int pe = i >> 10; int pr = pe % 24; int e = pe / 24;
        int n = (pr * 2 + (r >> 1)) * 8 + (lane >> 2);
        int k = kt * 16 + (lane & 3) * 2 + (r & 1) * 8;
        float v0 = 0.f, v1 = 0.f;
        if (n < HID_) {
            v0 = w1[((size_t)(e * C_ + k)) * HID_ + n];
            v1 = w1[((size_t)(e * C_ + k + 1)) * HID_ + n];
        }
        g_w1k[i] = pkbf(v0, v1);
    } else if (i < 196608) {         // w2k: [e][3 ch][8 pr over C][8 kc over hid-chunk]
        int j = i - 98304;
        int e = j / 24576; int rem = j % 24576;
        int ch = rem >> 13; int r2 = rem & 8191;
        int pr = r2 >> 10; int kc = (r2 >> 7) & 7;
        int lane = (r2 >> 2) & 31; int r = r2 & 3;
        int n = (pr * 2 + (r >> 1)) * 8 + (lane >> 2);
        int hid = ch * 128 + kc * 16 + (lane & 3) * 2 + (r & 1) * 8;
        float v0 = (hid < HID_)     ? w2[((size_t)(e * HID_ + hid)) * C_ + n]     : 0.f;
        float v1 = (hid + 1 < HID_) ? w2[((size_t)(e * HID_ + hid + 1)) * C_ + n] : 0.f;
        g_w2k[j] = pkbf(v0, v1);
    } else if (i < 212992) {         // conv frags (needs g_WbT)
        int j = i - 196608;
        int r = j & 3, lane = (j >> 2) & 31, kt = (j >> 7) & 7;
        int pe = j >> 10; int pr = pe & 7; int b = pe >> 3;
        int n = (pr * 2 + (r >> 1)) * 8 + (lane >> 2);
        int k = kt * 16 + (lane & 3) * 2 + (r & 1) * 8;
        float v0 = g_WbT[b * 16384 + k * 128 + n];
        float v1 = g_WbT[b * 16384 + (k + 1) * 128 + n];
        g_wck[j] = pkbf(v0, v1);
    }
}

// ---------------- K3: 1x1 conv (mma.sync) + gating + top-2 scatter ----------------
#define CVP    130
#define CV_WG  8320
#define CV_LG  8832
#define CV_SA  9088
#define CV_TOT 13184
#define CV_BYTES (CV_TOT * 4)

__global__ void __launch_bounds__(256, 2) k_conv_gate(const float* __restrict__ x,
                                                      const float* __restrict__ w_gate) {
    extern __shared__ __align__(16) u32 cvsm[];
    float* s_x  = (float*)cvsm;
    float* s_wg = (float*)(cvsm + CV_WG);
    float* s_lg = (float*)(cvsm + CV_LG);
    u32*   s_a  = cvsm + CV_SA;
    int t = threadIdx.x;
    int n0 = blockIdx.x * 64;
    int b = n0 / HW_; int hw0 = n0 % HW_;
    const float* xb = x + (size_t)b * C_ * HW_ + hw0;
    s_wg[t] = w_gate[t]; s_wg[t + 256] = w_gate[t + 256];
    #pragma unroll
    for (int i = 0; i < 32; i++) {
        int idx = t + i * 256; int c = idx >> 6, tk = idx & 63;
        s_x[tk * CVP + c] = xb[(size_t)c * HW_ + tk];
    }
    __syncthreads();
    {
        int e = t >> 6, tk = t & 63;
        const float* xr = s_x + tk * CVP;
        float a0 = 0.f, a1 = 0.f, a2 = 0.f, a3 = 0.f;
        #pragma unroll
        for (int c = 0; c < C_; c += 4) {
            a0 = fmaf(xr[c],     s_wg[c * 4 + e],       a0);
            a1 = fmaf(xr[c + 1], s_wg[(c + 1) * 4 + e], a1);
            a2 = fmaf(xr[c + 2], s_wg[(c + 2) * 4 + e], a2);
            a3 = fmaf(xr[c + 3], s_wg[(c + 3) * 4 + e], a3);
        }
        s_lg[tk * 4 + e] = (a0 + a1) + (a2 + a3);
    }
    #pragma unroll
    for (int i = 0; i < 16; i++) {
        int idx = t + i * 256;
        int m = idx >> 6, cp = idx & 63, c = cp * 2;
        float2 v = *(const float2*)(s_x + m * CVP + c);
        int mt = m >> 4, mr = m & 15, gg = mr & 7, hi = mr >> 3;
        int kt = c >> 4, ko = c & 15, half = ko >> 3, tg = (ko & 7) >> 1;
        int lane = gg * 4 + tg, reg = half * 2 + hi;
        s_a[((mt * 8 + kt) * 32 + lane) * 4 + reg] = pkbf(v.x, v.y);
    }
    __syncthreads();
    if (t < 64) {
        float l[4];
        #pragma unroll
        for (int e = 0; e < 4; e++) l[e] = s_lg[t * 4 + e];
        int e0 = 0; float m0 = l[0];
        #pragma unroll
        for (int e = 1; e < 4; e++) if (l[e] > m0) { m0 = l[e]; e0 = e; }
        int e1 = (e0 == 0) ? 1 : 0; float m1 = l[e1];
        #pragma unroll
        for (int e = 0; e < 4; e++) if (e != e0 && l[e] > m1) { m1 = l[e]; e1 = e; }
        float ex = expf(m1 - m0);
        float g0 = 1.0f / (1.0f + ex);
        float g1 = ex * g0;
        int n = n0 + t;
        int p0 = atomicAdd(&g_cnt[e0], 1);
        g_tok[e0 * N_ + p0] = n; g_gate[e0 * N_ + p0] = g0;
        g_slot[n * 2 + 0] = e0 * N_ + p0;
        int p1 = atomicAdd(&g_cnt[e1], 1);
        g_tok[e1 * N_ + p1] = n; g_gate[e1 * N_ + p1] = g1;
        g_slot[n * 2 + 1] = e1 * N_ + p1;
    }
    int warp = t >> 5, lane = t & 31, gg = lane >> 2, tg = lane & 3;
    int mt = warp & 3, nh = warp >> 2;
    float acc[8][4];
    #pragma unroll
    for (int nt = 0; nt < 8; nt++)
        #pragma unroll
        for (int r = 0; r < 4; r++) acc[nt][r] = 0.f;
    const u32* wbase = g_wck + (b * 8 + nh * 4) * 1024 + lane * 4;
    #pragma unroll
    for (int kt = 0; kt < 8; kt++) {
        uint4 A = *(const uint4*)(s_a + ((mt * 8 + kt) * 32 + lane) * 4);
        #pragma unroll
        for (int j = 0; j < 4; j++) {
            uint4 Bv = *(const uint4*)(wbase + j * 1024 + kt * 128);
            mma_bf16(acc[2*j],   A.x, A.y, A.z, A.w, Bv.x, Bv.y);
            mma_bf16(acc[2*j+1], A.x, A.y, A.z, A.w, Bv.z, Bv.w);
        }
    }
    int m0 = mt * 16 + gg, m1 = m0 + 8;
    u32* o0 = g_tyb + (size_t)(n0 + m0) * 64;
    u32* o1 = g_tyb + (size_t)(n0 + m1) * 64;
    #pragma unroll
    for (int nt = 0; nt < 8; nt++) {
        int cp = (nh * 8 + nt) * 4 + tg;
        o0[cp] = pkbf(acc[nt][0], acc[nt][1]);
        o1[cp] = pkbf(acc[nt][2], acc[nt][3]);
    }
}

// ======== K4: routed expert, 128 tok/CTA, 512 thr, smem-staged weights ========
// 16 warps = 4 m-groups (m32) x 4 n-quarters. hid chunked 3 x 128.
// smem u32: s_a 8192 | s_h 8192 | s_w1 8192 | s_w2 8192 | g/tk/b1/b2 512
#define XS_A   0
#define XS_H   8192
#define XS_W1  16384
#define XS_W2  24576
#define XS_G   32768
#define XS_TK  32896
#define XS_B1  33024
#define XS_B2  33152
#define XS_TOT 33280
#define XB_BYTES (XS_TOT * 4)

__global__ void __launch_bounds__(512, 1) k_expert(const float* __restrict__ b1,
                                                   const float* __restrict__ b2) {
    extern __shared__ __align__(16) u32 xs[];
    u32*   s_a  = xs + XS_A;
    u32*   s_h  = xs + XS_H;
    u32*   s_w1 = xs + XS_W1;
    u32*   s_w2 = xs + XS_W2;
    float* s_g  = (float*)(xs + XS_G);
    int*   s_tk = (int*)(xs + XS_TK);
    float* s_b1 = (float*)(xs + XS_B1);
    float* s_b2 = (float*)(xs + XS_B2);

    int e = blockIdx.y;
    int cnt = g_cnt[e];
    int start = blockIdx.x * 128;
    if (start >= cnt) return;
    int t = threadIdx.x;
    if (t < 128) {
        int idx = start + t;
        s_tk[t] = (idx < cnt) ? g_tok[e * N_ + idx] : 0;
        s_g[t]  = (idx < cnt) ? g_gate[e * N_ + idx] : 0.f;
        s_b2[t] = b2[e * C_ + t];
    }
    __syncthreads();
    // gather 128 tokens of bf16x2 ty into A-fragment layout
    #pragma unroll
    for (int i = 0; i < 16; i++) {
        int idx = t + i * 512;             // 128 tok x 64 col-pairs
        int m = idx >> 6, cp = idx & 63, c = cp * 2;
        u32 v = g_tyb[(size_t)s_tk[m] * 64 + cp];
        int mi = m >> 4, mr = m & 15, gg = mr & 7, hi = mr >> 3;
        int kt = c >> 4, ko = c & 15, half = ko >> 3, tg2 = (ko & 7) >> 1;
        int lane = gg * 4 + tg2, reg = half * 2 + hi;
        s_a[((mi * 8 + kt) * 32 + lane) * 4 + reg] = v;
    }
    int wid = t >> 5, lane = t & 31, gg = lane >> 2, tg = lane & 3;
    int mg = wid >> 2, nh = wid & 3;

    // persistent fc2 accumulators, bias-initialized: out[mi][p*2+q][4]
    float out[2][4][4];
    #pragma unroll
    for (int p = 0; p < 2; p++)
        #pragma unroll
        for (int q = 0; q < 2; q++) {
            int c = (nh * 2 + p) * 16 + q * 8 + tg * 2;
            float bx = s_b2[c], by = s_b2[c + 1];
            #pragma unroll
            for (int mi = 0; mi < 2; mi++) {
                out[mi][p * 2 + q][0] = bx; out[mi][p * 2 + q][1] = by;
                out[mi][p * 2 + q][2] = bx; out[mi][p * 2 + q][3] = by;
            }
        }

    for (int ch = 0; ch < 3; ch++) {
        __syncthreads();                    // prev fc2 done with s_w2 / gather done
        {   // stage weight chunks (coalesced) + b1 chunk
            const uint4* s1 = (const uint4*)(g_w1k + (e * 24 + ch * 8) * 1024);
            const uint4* s2 = (const uint4*)(g_w2k + (e * 3 + ch) * 8192);
            #pragma unroll
            for (int i = 0; i < 4; i++) ((uint4*)s_w1)[t + i * 512] = s1[t + i * 512];
            #pragma unroll
            for (int i = 0; i < 4; i++) ((uint4*)s_w2)[t + i * 512] = s2[t + i * 512];
            if (t < 128) {
                int hid = ch * 128 + t;
                s_b1[t] = (hid < HID_) ? b1[e * HID_ + hid] : 0.f;
            }
        }
        __syncthreads();
        // ---- fc1: hid-chunk n-range per warp = 32, m32 ----
        float acc[2][4][4];
        #pragma unroll
        for (int p = 0; p < 2; p++)
            #pragma unroll
            for (int q = 0; q < 2; q++) {
                int n = (nh * 2 + p) * 16 + q * 8 + tg * 2;
                float bx = s_b1[n], by = s_b1[n + 1];
                #pragma unroll
                for (int mi = 0; mi < 2; mi++) {
                    acc[mi][p * 2 + q][0] = bx; acc[mi][p * 2 + q][1] = by;
                    acc[mi][p * 2 + q][2] = bx; acc[mi][p * 2 + q][3] = by;
                }
            }
        #pragma unroll
        for (int kt = 0; kt < 8; kt++) {
            uint4 A0 = *(const uint4*)(s_a + ((mg * 2)     * 8 + kt) * 128 + lane * 4);
            uint4 A1 = *(const uint4*)(s_a + ((mg * 2 + 1) * 8 + kt) * 128 + lane * 4);
            #pragma unroll
            for (int p = 0; p < 2; p++) {
                uint4 Bv = *(const uint4*)(s_w1 + ((nh * 2 + p) * 8 + kt) * 128 + lane * 4);
                mma_bf16(acc[0][2*p],   A0.x, A0.y, A0.z, A0.w, Bv.x, Bv.y);
                mma_bf16(acc[0][2*p+1], A0.x, A0.y, A0.z, A0.w, Bv.z, Bv.w);
                mma_bf16(acc[1][2*p],   A1.x, A1.y, A1.z, A1.w, Bv.x, Bv.y);
                mma_bf16(acc[1][2*p+1], A1.x, A1.y, A1.z, A1.w, Bv.z, Bv.w);
            }
        }
        // gelu + pack: fc1 acc frag pair == fc2 A frag
        #pragma unroll
        for (int mi = 0; mi < 2; mi++)
            #pragma unroll
            for (int p = 0; p < 2; p++) {
                uint4 o;
                o.x = pkbf(gelu_exact(acc[mi][2*p][0]),   gelu_exact(acc[mi][2*p][1]));
                o.y = pkbf(gelu_exact(acc[mi][2*p][2]),   gelu_exact(acc[mi][2*p][3]));
                o.z = pkbf(gelu_exact(acc[mi][2*p+1][0]), gelu_exact(acc[mi][2*p+1][1]));
                o.w = pkbf(gelu_exact(acc[mi][2*p+1][2]), gelu_exact(acc[mi][2*p+1][3]));
                *(uint4*)(s_h + ((mg * 2 + mi) * 8 + nh * 2 + p) * 128 + lane * 4) = o;
            }
        __syncthreads();
        // ---- fc2: K = this hid chunk (8 kc), N-quarter = 32 cols, m32 ----
        #pragma unroll
        for (int kc = 0; kc < 8; kc++) {
            uint4 A0 = *(const uint4*)(s_h + ((mg * 2)     * 8 + kc) * 128 + lane * 4);
            uint4 A1 = *(const uint4*)(s_h + ((mg * 2 + 1) * 8 + kc) * 128 + lane * 4);
            #pragma unroll
            for (int p = 0; p < 2; p++) {
                uint4 Bv = *(const uint4*)(s_w2 + ((nh * 2 + p) * 8 + kc) * 128 + lane * 4);
                mma_bf16(out[0][2*p],   A0.x, A0.y, A0.z, A0.w, Bv.x, Bv.y);
                mma_bf16(out[0][2*p+1], A0.x, A0.y, A0.z, A0.w, Bv.z, Bv.w);
                mma_bf16(out[1][2*p],   A1.x, A1.y, A1.z, A1.w, Bv.x, Bv.y);
                mma_bf16(out[1][2*p+1], A1.x, A1.y, A1.z, A1.w, Bv.z, Bv.w);
            }
        }
    }
    __syncthreads();                        // s_h free for epilogue staging
    // epilogue: gate * out -> s_h (bf16x2 [tok][cp]) -> coalesced copy out
    #pragma unroll
    for (int mi = 0; mi < 2; mi++) {
        int row0 = (mg * 2 + mi) * 16 + gg, row1 = row0 + 8;
        float g0 = s_g[row0], g1 = s_g[row1];
        #pragma unroll
        for (int p = 0; p < 2; p++)
            #pragma unroll
            for (int q = 0; q < 2; q++) {
                int cp = (nh * 2 + p) * 8 + q * 4 + tg;
                s_h[row0 * 64 + cp] = pkbf(g0 * out[mi][2*p+q][0], g0 * out[mi][2*p+q][1]);
                s_h[row1 * 64 + cp] = pkbf(g1 * out[mi][2*p+q][2], g1 * out[mi][2*p+q][3]);
            }
    }
    __syncthreads();
    u32* op = g_obufh + (size_t)(e * N_ + start) * 64;
    #pragma unroll
    for (int i = 0; i < 4; i++)
        ((uint4*)op)[t + i * 512] = ((const uint4*)s_h)[t + i * 512];
}

// ------------------- K5: combine slots + residual, NCHW -------------------
__global__ void __launch_bounds__(256) k_combine(const float* __restrict__ x,
                                                 float* __restrict__ dout) {
    __shared__ float s_y[C_ * 66];
    __shared__ int s_sl[128];
    int t = threadIdx.x;
    int n0 = blockIdx.x * 64;
    int b = n0 / HW_; int hw0 = n0 % HW_;
    if (t < 128) s_sl[t] = g_slot[n0 * 2 + t];
    __syncthreads();
    #pragma unroll
    for (int i = 0; i < 16; i++) {
        int idx = t + i * 256; int ts = idx >> 6, cp = idx & 63, c = cp * 2;
        int s0 = s_sl[ts * 2], s1 = s_sl[ts * 2 + 1];
        float2 a = upbf(g_obufh[(size_t)s0 * 64 + cp]);
        float2 bb = upbf(g_obufh[(size_t)s1 * 64 + cp]);
        s_y[c * 66 + ts]       = a.x + bb.x;
        s_y[(c + 1) * 66 + ts] = a.y + bb.y;
    }
    __syncthreads();
    size_t base = (size_t)b * C_ * HW_ + hw0;
    #pragma unroll
    for (int i = 0; i < 16; i++) {
        int lin = t + i * 256; int c = lin >> 5, k = lin & 31;
        size_t idx = base + (size_t)c * HW_ + 2 * k;
        float2 xv = *(const float2*)(x + idx);
        float2 yv = *(const float2*)(s_y + c * 66 + 2 * k);
        *(float2*)(dout + idx) = make_float2(yv.x + xv.x, yv.y + xv.y);
    }
}

// ------------------------------- K6: aux loss -------------------------------
__global__ void k_loss(float* __restrict__ dout, int has_loss) {
    __shared__ float s_imp[E_];
    int t = threadIdx.x;
    int e = t >> 5, lane = t & 31;
    if (t < 128) {
        int cnt = g_cnt[e];
        float s = 0.f;
        for (int i = lane; i < cnt; i += 32) s += g_gate[e * N_ + i];
        #pragma unroll
        for (int o = 16; o > 0; o >>= 1) s += __shfl_xor_sync(0xffffffff, s, o);
        if (lane == 0) s_imp[e] = s;
    }
    __syncthreads();
    if (t == 0 && has_loss) {
        float mi = 0.f, ml = 0.f;
        float I[E_], L[E_];
        for (int k = 0; k < E_; k++) {
            I[k] = s_imp[k]; L[k] = (float)g_cnt[k];
            mi += I[k]; ml += L[k];
        }
        mi *= 0.25f; ml *= 0.25f;
        float vi = 0.f, vl = 0.f;
        for (int k = 0; k < E_; k++) {
            float di = I[k] - mi, dl = L[k] - ml;
            vi += di * di; vl += dl * dl;
        }
        vi *= 0.25f; vl *= 0.25f;
        float loss = 1e-2f * (vi / (mi * mi + 1e-10f) + vl / (ml * ml + 1e-10f));
        dout[NCHW_] = loss;
    }
}

// --------------------------------- launcher ---------------------------------
extern "C" void kernel_launch(void* const* d_in, const int* in_sizes, int n_in,
                              void* d_out, int out_size) {
    const float* x      = (const float*)d_in[0];
    const float* prompt = (const float*)d_in[1];
    const float* w_lin  = (const float*)d_in[2];
    const float* b_lin  = (const float*)d_in[3];
    const float* w_conv = (const float*)d_in[4];
    const float* w_gate = (const float*)d_in[5];
    const float* w1     = (const float*)d_in[6];
    const float* b1     = (const float*)d_in[7];
    const float* w2     = (const float*)d_in[8];
    const float* b2     = (const float*)d_in[9];
    float* out = (float*)d_out;

    cudaFuncSetAttribute(k_conv_gate, cudaFuncAttributeMaxDynamicSharedMemorySize, CV_BYTES);
    cudaFuncSetAttribute(k_expert, cudaFuncAttributeMaxDynamicSharedMemorySize, XB_BYTES);

    k_mean1<<<1024, 256>>>(x);
    k_prep<<<1, 256>>>(prompt, w_lin, b_lin, w_conv);
    k_pack<<<832, 256>>>(w1, w2);
    k_conv_gate<<<N_ / 64, 256, CV_BYTES>>>(x, w_gate);
    dim3 ge(N_ / 128, E_);
    k_expert<<<ge, 512, XB_BYTES>>>(b1, b2);
    k_combine<<<N_ / 64, 256>>>(x, out);
    k_loss<<<1, 128>>>(out, (out_size > NCHW_) ? 1 : 0);
}

// round 14
// speedup vs baseline: 1.2021x; 1.1588x over previous
#include <cuda_runtime.h>
#include <cuda_bf16.h>
#include <math.h>

#define B_     2
#define C_     128
#define HW_    36864
#define N_     73728
#define E_     4
#define HID_   340
#define NCHW_  9437184

typedef unsigned long long u64;
typedef unsigned int u32;
typedef unsigned short u16;

__device__ __forceinline__ float gelu_exact(float v) {
    return 0.5f * v * (1.0f + erff(v * 0.70710678118654752440f));
}
__device__ __forceinline__ u32 pkbf(float lo, float hi) {
    u32 d; asm("cvt.rn.bf16x2.f32 %0, %1, %2;" : "=r"(d) : "f"(hi), "f"(lo)); return d;
}
__device__ __forceinline__ float2 upbf(u32 v) {
    __nv_bfloat162 b = *(__nv_bfloat162*)&v;
    return __bfloat1622float2(b);
}
__device__ __forceinline__ void mma_bf16(float* c,
                                         u32 a0, u32 a1, u32 a2, u32 a3, u32 b0, u32 b1) {
    asm("mma.sync.aligned.m16n8k16.row.col.f32.bf16.bf16.f32 "
        "{%0,%1,%2,%3}, {%4,%5,%6,%7}, {%8,%9}, {%0,%1,%2,%3};"
        : "+f"(c[0]), "+f"(c[1]), "+f"(c[2]), "+f"(c[3])
        : "r"(a0), "r"(a1), "r"(a2), "r"(a3), "r"(b0), "r"(b1));
}
__device__ __forceinline__ void imma8(int* c,
                                      u32 a0, u32 a1, u32 a2, u32 a3, u32 b0, u32 b1) {
    asm("mma.sync.aligned.m16n8k32.row.col.s32.s8.s8.s32 "
        "{%0,%1,%2,%3}, {%4,%5,%6,%7}, {%8,%9}, {%0,%1,%2,%3};"
        : "+r"(c[0]), "+r"(c[1]), "+r"(c[2]), "+r"(c[3])
        : "r"(a0), "r"(a1), "r"(a2), "r"(a3), "r"(b0), "r"(b1));
}
__device__ __forceinline__ u16 pk2s8(float a, float b) {
    int qa = __float2int_rn(a); qa = max(-127, min(127, qa));
    int qb = __float2int_rn(b); qb = max(-127, min(127, qb));
    return (u16)((qa & 0xFF) | ((qb & 0xFF) << 8));
}

// ----------------------------- device scratch -----------------------------
__device__ float g_part[1024];
__device__ float g_emb[B_ * C_];
__device__ float g_WbT[B_ * C_ * C_];           // [b][c][o]
__device__ u32   g_ty8[(size_t)N_ * 32];        // conv-out tokens, s8 [n][128 bytes]
__device__ int   g_cnt[E_];
__device__ int   g_tok[E_ * N_];
__device__ float g_gate[E_ * N_];
__device__ int   g_slot[N_ * 2];
__device__ u32   g_obufh[(size_t)E_ * N_ * 64]; // gated expert outputs, bf16x2
__device__ u32   g_wck[16384];                  // conv weights, bf16 frag order
__device__ u32   g_w1q[49152];                  // s8 [e][48pr][4kt][32lane][2]
__device__ u32   g_w2q[49152];                  // s8 [e][16pr][12kt][32lane][2]
__device__ float g_red[16];                     // reductions
__device__ float g_scl[20];                     // final scales

// ---------------------- K1: channel means (stage 1) ----------------------
__global__ void k_mean1(const float* __restrict__ x) {
    int part = blockIdx.x;
    int row = part >> 2, q = part & 3;
    int t = threadIdx.x;
    const float4* xr = (const float4*)(x + (size_t)row * HW_) + q * 2304;
    float s = 0.f;
    #pragma unroll
    for (int i = 0; i < 9; i++) {
        float4 v = xr[t + i * 256];
        s += (v.x + v.y) + (v.z + v.w);
    }
    __shared__ float sm[256];
    sm[t] = s; __syncthreads();
    for (int o = 128; o > 0; o >>= 1) {
        if (t < o) sm[t] += sm[t + o];
        __syncthreads();
    }
    if (t == 0) g_part[part] = sm[0];
}

// ------ K2: mean reduce + prompt softmax + fold conv W ------
__global__ void k_prep(const float* __restrict__ prompt, const float* __restrict__ w_lin,
                       const float* __restrict__ b_lin, const float* __restrict__ w_conv) {
    int t = threadIdx.x;
    __shared__ float s_l[B_ * 5], s_pw[B_ * 5], s_sp[B_ * C_];
    {
        float4 p = *(const float4*)(g_part + t * 4);
        g_emb[t] = ((p.x + p.y) + (p.z + p.w)) * (1.0f / (float)HW_);
    }
    if (t < E_) g_cnt[t] = 0;
    __syncthreads();
    if (t < B_ * 5) {
        int b = t / 5, p = t % 5;
        float a = b_lin[p];
        for (int c = 0; c < C_; c++) a += g_emb[b * C_ + c] * w_lin[p * C_ + c];
        s_l[t] = a;
    }
    __syncthreads();
    if (t < B_) {
        float m = s_l[t * 5];
        for (int p = 1; p < 5; p++) m = fmaxf(m, s_l[t * 5 + p]);
        float e[5]; float den = 0.f;
        for (int p = 0; p < 5; p++) { e[p] = expf(s_l[t * 5 + p] - m); den += e[p]; }
        for (int p = 0; p < 5; p++) s_pw[t * 5 + p] = e[p] / den;
    }
    __syncthreads();
    {
        int b = t >> 7, c = t & 127;
        float a = 0.f;
        for (int p = 0; p < 5; p++) a += s_pw[b * 5 + p] * prompt[p * C_ + c];
        s_sp[t] = a;
    }
    __syncthreads();
    for (int i = t; i < B_ * C_ * C_; i += 256) {
        int b = i >> 14; int rem = i & 16383; int c = rem >> 7; int o = rem & 127;
        g_WbT[i] = w_conv[o * C_ + c] * s_sp[b * C_ + c];
    }
}

// --------------- K2c: reductions for quantization scales ---------------
__global__ void k_scale1(const float* __restrict__ w1, const float* __restrict__ w2) {
    int blk = blockIdx.x, t = threadIdx.x;
    __shared__ float sm[256], sm2[256];
    if (blk < 4) {
        const float* w = w1 + (size_t)blk * C_ * HID_;
        float mx = 0.f, ss = 0.f;
        for (int i = t; i < C_ * HID_; i += 256) { float v = w[i]; mx = fmaxf(mx, fabsf(v)); ss += v * v; }
        sm[t] = mx; sm2[t] = ss; __syncthreads();
        for (int o = 128; o > 0; o >>= 1) {
            if (t < o) { sm[t] = fmaxf(sm[t], sm[t + o]); sm2[t] += sm2[t + o]; }
            __syncthreads();
        }
        if (t == 0) { g_red[blk] = sm[0]; g_red[8 + blk] = sm2[0]; }
    } else if (blk < 8) {
        int e = blk - 4;
        const float* w = w2 + (size_t)e * HID_ * C_;
        float mx = 0.f;
        for (int i = t; i < C_ * HID_; i += 256) mx = fmaxf(mx, fabsf(w[i]));
        sm[t] = mx; __syncthreads();
        for (int o = 128; o > 0; o >>= 1) {
            if (t < o) sm[t] = fmaxf(sm[t], sm[t + o]);
            __syncthreads();
        }
        if (t == 0) g_red[4 + e] = sm[0];
    } else {
        int b = t >> 7, o = t & 127;
        float ss = 0.f;
        for (int c = 0; c < C_; c++) { float v = g_WbT[b * 16384 + c * 128 + o]; ss += v * v; }
        sm[t] = ss; sm2[t] = ss; __syncthreads();
        for (int off = 64; off > 0; off >>= 1) {
            if ((t & 127) < off) { sm[t] = fmaxf(sm[t], sm[t + off]); sm2[t] += sm2[t + off]; }
            __syncthreads();
        }
        if ((t & 127) == 0) { g_red[12 + b] = sqrtf(sm[t]); g_red[14 + b] = sm2[t] * (1.f / 128.f); }
    }
}

__global__ void k_scale2() {
    if (threadIdx.x == 0) {
        for (int b = 0; b < 2; b++) g_scl[b] = 8.f * g_red[12 + b] / 127.f;       // dt
        for (int e = 0; e < 4; e++) g_scl[2 + e] = g_red[e] / 127.f;              // S1
        for (int e = 0; e < 4; e++) g_scl[6 + e] = g_red[4 + e] / 127.f;          // S2
        for (int b = 0; b < 2; b++)
            for (int e = 0; e < 4; e++) {
                float sh = 0.5f * sqrtf(g_red[14 + b] * g_red[8 + e] / 340.f);
                g_scl[10 + b * 4 + e] = 8.f * sh / 127.f;                         // dh
            }
    }
}

// ----------------- K2b: pack weights (s8 frags + conv bf16 frags) -----------------
__global__ void k_packq(const float* __restrict__ w1, const float* __restrict__ w2) {
    int i = blockIdx.x * 256 + threadIdx.x;
    if (i < 49152) {                 // w1q: n over hid (48 pr), k over C (4 kt32)
        int e = i / 12288; int rem = i % 12288;
        int pr = rem / 256; int r2 = rem % 256;
        int kt = r2 >> 6; int lane = (r2 >> 1) & 31; int r = r2 & 1;
        int n = pr * 8 + (lane >> 2);
        int kb = kt * 32 + (lane & 3) * 4 + r * 16;
        u32 pkv = 0;
        if (n < HID_) {
            float inv = 127.f / g_red[e];
            #pragma unroll
            for (int bb = 0; bb < 4; bb++) {
                float v = w1[((size_t)(e * C_ + kb + bb)) * HID_ + n] * inv;
                int q = __float2int_rn(v); q = max(-127, min(127, q));
                pkv |= ((u32)q & 0xFF) << (8 * bb);
            }
        }
        g_w1q[i] = pkv;
    } else if (i < 98304) {          // w2q: n over C (16 pr), k over hid (12 kt32)
        int j = i - 49152;
        int e = j / 12288; int rem = j % 12288;
        int pr = rem / 768; int r2 = rem % 768;
        int kt = r2 / 64; int r3 = r2 % 64;
        int lane = r3 >> 1; int r = r3 & 1;
        int n = pr * 8 + (lane >> 2);
        int kb = kt * 32 + (lane & 3) * 4 + r * 16;
        float inv = 127.f / g_red[4 + e];
        u32 pkv = 0;
        #pragma unroll
        for (int bb = 0; bb < 4; bb++) {
            int k = kb + bb;
            if (k < HID_) {
                float v = w2[((size_t)(e * HID_ + k)) * C_ + n] * inv;
                int q = __float2int_rn(v); q = max(-127, min(127, q));
                pkv |= ((u32)q & 0xFF) << (8 * bb);
            }
        }
        g_w2q[j] = pkv;
    } else if (i < 114688) {         // conv bf16 frags (needs g_WbT)
        int j = i - 98304;
        int r = j & 3, lane = (j >> 2) & 31, kt = (j >> 7) & 7;
        int pe = j >> 10; int pr = pe & 7; int b = pe >> 3;
        int n = (pr * 2 + (r >> 1)) * 8 + (lane >> 2);
        int k = kt * 16 + (lane & 3) * 2 + (r & 1) * 8;
        float v0 = g_WbT[b * 16384 + k * 128 + n];
        float v1 = g_WbT[b * 16384 + (k + 1) * 128 + n];
        g_wck[j] = pkbf(v0, v1);
    }
}

// ---------------- K3: 1x1 conv (bf16 HMMA) + gating + top-2 scatter ----------------
#define CVP    130
#define CV_WG  8320
#define CV_LG  8832
#define CV_SA  9088
#define CV_TOT 13184
#define CV_BYTES (CV_TOT * 4)

__global__ void __launch_bounds__(256, 2) k_conv_gate(const float* __restrict__ x,
                                                      const float* __restrict__ w_gate) {
    extern __shared__ __align__(16) u32 cvsm[];
    float* s_x  = (float*)cvsm;
    float* s_wg = (float*)(cvsm + CV_WG);
    float* s_lg = (float*)(cvsm + CV_LG);
    u32*   s_a  = cvsm + CV_SA;
    int t = threadIdx.x;
    int n0 = blockIdx.x * 64;
    int b = n0 / HW_; int hw0 = n0 % HW_;
    const float* xb = x + (size_t)b * C_ * HW_ + hw0;
    s_wg[t] = w_gate[t]; s_wg[t + 256] = w_gate[t + 256];
    #pragma unroll
    for (int i = 0; i < 32; i++) {
        int idx = t + i * 256; int c = idx >> 6, tk = idx & 63;
        s_x[tk * CVP + c] = xb[(size_t)c * HW_ + tk];
    }
    __syncthreads();
    {
        int e = t >> 6, tk = t & 63;
        const float* xr = s_x + tk * CVP;
        float a0 = 0.f, a1 = 0.f, a2 = 0.f, a3 = 0.f;
        #pragma unroll
        for (int c = 0; c < C_; c += 4) {
            a0 = fmaf(xr[c],     s_wg[c * 4 + e],       a0);
            a1 = fmaf(xr[c + 1], s_wg[(c + 1) * 4 + e], a1);
            a2 = fmaf(xr[c + 2], s_wg[(c + 2) * 4 + e], a2);
            a3 = fmaf(xr[c + 3], s_wg[(c + 3) * 4 + e], a3);
        }
        s_lg[tk * 4 + e] = (a0 + a1) + (a2 + a3);
    }
    #pragma unroll
    for (int i = 0; i < 16; i++) {
        int idx = t + i * 256;
        int m = idx >> 6, cp = idx & 63, c = cp * 2;
        float2 v = *(const float2*)(s_x + m * CVP + c);
        int mt = m >> 4, mr = m & 15, gg = mr & 7, hi = mr >> 3;
        int kt = c >> 4, ko = c & 15, half = ko >> 3, tg = (ko & 7) >> 1;
        int lane = gg * 4 + tg, reg = half * 2 + hi;
        s_a[((mt * 8 + kt) * 32 + lane) * 4 + reg] = pkbf(v.x, v.y);
    }
    __syncthreads();
    if (t < 64) {
        float l[4];
        #pragma unroll
        for (int e = 0; e < 4; e++) l[e] = s_lg[t * 4 + e];
        int e0 = 0; float m0 = l[0];
        #pragma unroll
        for (int e = 1; e < 4; e++) if (l[e] > m0) { m0 = l[e]; e0 = e; }
        int e1 = (e0 == 0) ? 1 : 0; float m1 = l[e1];
        #pragma unroll
        for (int e = 0; e < 4; e++) if (e != e0 && l[e] > m1) { m1 = l[e]; e1 = e; }
        float ex = expf(m1 - m0);
        float g0 = 1.0f / (1.0f + ex);
        float g1 = ex * g0;
        int n = n0 + t;
        int p0 = atomicAdd(&g_cnt[e0], 1);
        g_tok[e0 * N_ + p0] = n; g_gate[e0 * N_ + p0] = g0;
        g_slot[n * 2 + 0] = e0 * N_ + p0;
        int p1 = atomicAdd(&g_cnt[e1], 1);
        g_tok[e1 * N_ + p1] = n; g_gate[e1 * N_ + p1] = g1;
        g_slot[n * 2 + 1] = e1 * N_ + p1;
    }
    int warp = t >> 5, lane = t & 31, gg = lane >> 2, tg = lane & 3;
    int mt = warp & 3, nh = warp >> 1 & 1 ? (warp >> 2) : (warp >> 2); // placate
    nh = warp >> 2;
    float acc[8][4];
    #pragma unroll
    for (int nt = 0; nt < 8; nt++)
        #pragma unroll
        for (int r = 0; r < 4; r++) acc[nt][r] = 0.f;
    const u32* wbase = g_wck + (b * 8 + nh * 4) * 1024 + lane * 4;
    #pragma unroll
    for (int kt = 0; kt < 8; kt++) {
        uint4 A = *(const uint4*)(s_a + ((mt * 8 + kt) * 32 + lane) * 4);
        #pragma unroll
        for (int j = 0; j < 4; j++) {
            uint4 Bv = *(const uint4*)(wbase + j * 1024 + kt * 128);
            mma_bf16(acc[2*j],   A.x, A.y, A.z, A.w, Bv.x, Bv.y);
            mma_bf16(acc[2*j+1], A.x, A.y, A.z, A.w, Bv.z, Bv.w);
        }
    }
    // quantize ty -> s8, per-batch scale
    float invt = 1.0f / g_scl[b];
    int m0 = mt * 16 + gg, m1 = m0 + 8;
    u16* o0 = (u16*)(g_ty8 + (size_t)(n0 + m0) * 32);
    u16* o1 = (u16*)(g_ty8 + (size_t)(n0 + m1) * 32);
    #pragma unroll
    for (int nt = 0; nt < 8; nt++) {
        int idx16 = (nh * 8 + nt) * 4 + tg;
        o0[idx16] = pk2s8(acc[nt][0] * invt, acc[nt][1] * invt);
        o1[idx16] = pk2s8(acc[nt][2] * invt, acc[nt][3] * invt);
    }
}

// ======== K4: routed expert, INT8 IMMA m16n8k32, 64 tok/CTA, 256 thr ========
// 8 warps = 2 mg (m32) x 4 nh. fc1: 48 pr x 4 kt; fc2: 16 pr x 12 kt.
#define QS_H    2048
#define QS_B1   8448
#define QS_B2   8832
#define QS_G    8960
#define QS_TK   9024
#define QS_S1   9088
#define QS_IDH  9152
#define QS_SO   9216
#define QS_TOT  9280
#define QX_BYTES (QS_TOT * 4)

__global__ void __launch_bounds__(256, 2) k_expert(const float* __restrict__ b1,
                                                   const float* __restrict__ b2) {
    extern __shared__ __align__(16) u32 qs[];
    u32*   s_a   = qs;                       // 2048: [4mt][4kt][32lane][4reg]
    u32*   s_h   = qs + QS_H;                // 6400: 64 rows x 100 u32 (s8 h)
    float* s_b1f = (float*)(qs + QS_B1);
    float* s_b2f = (float*)(qs + QS_B2);
    float* s_g   = (float*)(qs + QS_G);
    int*   s_tk  = (int*)(qs + QS_TK);
    float* s_s1  = (float*)(qs + QS_S1);
    float* s_idh = (float*)(qs + QS_IDH);
    float* s_so  = (float*)(qs + QS_SO);

    int e = blockIdx.y;
    int cnt = g_cnt[e];
    int start = blockIdx.x * 64;
    if (start >= cnt) return;
    int t = threadIdx.x;
    if (t < 64) {
        int idx = start + t;
        int tok = (idx < cnt) ? g_tok[e * N_ + idx] : 0;
        s_tk[t] = tok;
        s_g[t]  = (idx < cnt) ? g_gate[e * N_ + idx] : 0.f;
        int bb = tok / HW_;
        float dt = g_scl[bb], s1 = g_scl[2 + e];
        float dh = g_scl[10 + bb * 4 + e], s2 = g_scl[6 + e];
        s_s1[t]  = dt * s1;
        s_idh[t] = 1.f / dh;
        s_so[t]  = dh * s2;
    }
    if (t < 128) s_b2f[t] = b2[e * C_ + t];
    for (int i = t; i < 384; i += 256) s_b1f[i] = (i < HID_) ? b1[e * HID_ + i] : 0.f;
    __syncthreads();
    // gather q_ty -> s8 A-fragments
    #pragma unroll
    for (int i = 0; i < 8; i++) {
        int idx = t + i * 256; int m = idx >> 5, c4 = idx & 31;
        u32 v = g_ty8[(size_t)s_tk[m] * 32 + c4];
        int kt = c4 >> 3, r7 = c4 & 7, tgf = r7 & 3, half = r7 >> 2;
        int mt = m >> 4, mr = m & 15, g = mr & 7, hi = mr >> 3;
        s_a[((mt * 4 + kt) * 32 + g * 4 + tgf) * 4 + half * 2 + hi] = v;
    }
    __syncthreads();
    int wid = t >> 5, lane = t & 31, gg = lane >> 2, tg = lane & 3;
    int mg = wid >> 2, nh = wid & 3;
    u16* sh16 = (u16*)s_h;

    // ---- fc1: int8, 2 passes of 6 n8-tiles ----
    for (int pass = 0; pass < 2; pass++) {
        int acc[2][6][4];
        #pragma unroll
        for (int mi = 0; mi < 2; mi++)
            #pragma unroll
            for (int j = 0; j < 6; j++)
                #pragma unroll
                for (int r = 0; r < 4; r++) acc[mi][j][r] = 0;
        #pragma unroll
        for (int kt = 0; kt < 4; kt++) {
            uint4 A0 = *(const uint4*)(s_a + (((2 * mg) * 4 + kt) * 32 + lane) * 4);
            uint4 A1 = *(const uint4*)(s_a + (((2 * mg + 1) * 4 + kt) * 32 + lane) * 4);
            #pragma unroll
            for (int j = 0; j < 6; j++) {
                int pr = nh * 12 + pass * 6 + j;
                uint2 Bv = *(const uint2*)(g_w1q + ((e * 48 + pr) * 4 + kt) * 64 + lane * 2);
                imma8(acc[0][j], A0.x, A0.y, A0.z, A0.w, Bv.x, Bv.y);
                imma8(acc[1][j], A1.x, A1.y, A1.z, A1.w, Bv.x, Bv.y);
            }
        }
        #pragma unroll
        for (int mi = 0; mi < 2; mi++) {
            int m0 = (2 * mg + mi) * 16 + gg, m1 = m0 + 8;
            float sc0 = s_s1[m0], sc1 = s_s1[m1];
            float ih0 = s_idh[m0], ih1 = s_idh[m1];
            #pragma unroll
            for (int j = 0; j < 6; j++) {
                int pr = nh * 12 + pass * 6 + j;
                int n0 = pr * 8 + tg * 2;
                float b1a = s_b1f[n0], b1b = s_b1f[n0 + 1];
                float h00 = gelu_exact(__int2float_rn(acc[mi][j][0]) * sc0 + b1a);
                float h01 = gelu_exact(__int2float_rn(acc[mi][j][1]) * sc0 + b1b);
                float h10 = gelu_exact(__int2float_rn(acc[mi][j][2]) * sc1 + b1a);
                float h11 = gelu_exact(__int2float_rn(acc[mi][j][3]) * sc1 + b1b);
                sh16[m0 * 200 + (n0 >> 1)] = pk2s8(h00 * ih0, h01 * ih0);
                sh16[m1 * 200 + (n0 >> 1)] = pk2s8(h10 * ih1, h11 * ih1);
            }
        }
    }
    __syncthreads();

    // ---- fc2: int8, K=384 (12 kt32), warp n-quarter = 32 cols ----
    int out[2][4][4];
    #pragma unroll
    for (int mi = 0; mi < 2; mi++)
        #pragma unroll
        for (int p = 0; p < 4; p++)
            #pragma unroll
            for (int r = 0; r < 4; r++) out[mi][p][r] = 0;
    #pragma unroll
    for (int kt = 0; kt < 12; kt++) {
        u32 A[2][4];
        #pragma unroll
        for (int mi = 0; mi < 2; mi++) {
            int r0 = (2 * mg + mi) * 16 + gg;
            A[mi][0] = s_h[r0 * 100 + kt * 8 + tg];
            A[mi][1] = s_h[(r0 + 8) * 100 + kt * 8 + tg];
            A[mi][2] = s_h[r0 * 100 + kt * 8 + 4 + tg];
            A[mi][3] = s_h[(r0 + 8) * 100 + kt * 8 + 4 + tg];
        }
        #pragma unroll
        for (int p = 0; p < 4; p++) {
            uint2 Bv = *(const uint2*)(g_w2q + ((e * 16 + nh * 4 + p) * 12 + kt) * 64 + lane * 2);
            imma8(out[0][p], A[0][0], A[0][1], A[0][2], A[0][3], Bv.x, Bv.y);
            imma8(out[1][p], A[1][0], A[1][1], A[1][2], A[1][3], Bv.x, Bv.y);
        }
    }
    // ---- epilogue: dequant + bias + gate -> obufh bf16x2 ----
    #pragma unroll
    for (int mi = 0; mi < 2; mi++) {
        int m0 = (2 * mg + mi) * 16 + gg, m1 = m0 + 8;
        float so0 = s_so[m0], so1 = s_so[m1];
        float g0 = s_g[m0], g1 = s_g[m1];
        u32* o0 = g_obufh + (size_t)(e * N_ + start + m0) * 64;
        u32* o1 = g_obufh + (size_t)(e * N_ + start + m1) * 64;
        #pragma unroll
        for (int p = 0; p < 4; p++) {
            int n0 = (nh * 4 + p) * 8 + tg * 2;
            int cp = n0 >> 1;
            float v00 = __int2float_rn(out[mi][p][0]) * so0 + s_b2f[n0];
            float v01 = __int2float_rn(out[mi][p][1]) * so0 + s_b2f[n0 + 1];
            float v10 = __int2float_rn(out[mi][p][2]) * so1 + s_b2f[n0];
            float v11 = __int2float_rn(out[mi][p][3]) * so1 + s_b2f[n0 + 1];
            o0[cp] = pkbf(g0 * v00, g0 * v01);
            o1[cp] = pkbf(g1 * v10, g1 * v11);
        }
    }
}

// ------------------- K5: combine slots + residual, NCHW -------------------
__global__ void __launch_bounds__(256) k_combine(const float* __restrict__ x,
                                                 float* __restrict__ dout) {
    __shared__ float s_y[C_ * 66];
    __shared__ int s_sl[128];
    int t = threadIdx.x;
    int n0 = blockIdx.x * 64;
    int b = n0 / HW_; int hw0 = n0 % HW_;
    if (t < 128) s_sl[t] = g_slot[n0 * 2 + t];
    __syncthreads();
    #pragma unroll
    for (int i = 0; i < 16; i++) {
        int idx = t + i * 256; int ts = idx >> 6, cp = idx & 63, c = cp * 2;
        int s0 = s_sl[ts * 2], s1 = s_sl[ts * 2 + 1];
        float2 a = upbf(g_obufh[(size_t)s0 * 64 + cp]);
        float2 bb = upbf(g_obufh[(size_t)s1 * 64 + cp]);
        s_y[c * 66 + ts]       = a.x + bb.x;
        s_y[(c + 1) * 66 + ts] = a.y + bb.y;
    }
    __syncthreads();
    size_t base = (size_t)b * C_ * HW_ + hw0;
    #pragma unroll
    for (int i = 0; i < 16; i++) {
        int lin = t + i * 256; int c = lin >> 5, k = lin & 31;
        size_t idx = base + (size_t)c * HW_ + 2 * k;
        float2 xv = *(const float2*)(x + idx);
        float2 yv = *(const float2*)(s_y + c * 66 + 2 * k);
        *(float2*)(dout + idx) = make_float2(yv.x + xv.x, yv.y + xv.y);
    }
}

// ------------------------------- K6: aux loss -------------------------------
__global__ void k_loss(float* __restrict__ dout, int has_loss) {
    __shared__ float s_imp[E_];
    int t = threadIdx.x;
    int e = t >> 5, lane = t & 31;
    if (t < 128) {
        int cnt = g_cnt[e];
        float s = 0.f;
        for (int i = lane; i < cnt; i += 32) s += g_gate[e * N_ + i];
        #pragma unroll
        for (int o = 16; o > 0; o >>= 1) s += __shfl_xor_sync(0xffffffff, s, o);
        if (lane == 0) s_imp[e] = s;
    }
    __syncthreads();
    if (t == 0 && has_loss) {
        float mi = 0.f, ml = 0.f;
        float I[E_], L[E_];
        for (int k = 0; k < E_; k++) {
            I[k] = s_imp[k]; L[k] = (float)g_cnt[k];
            mi += I[k]; ml += L[k];
        }
        mi *= 0.25f; ml *= 0.25f;
        float vi = 0.f, vl = 0.f;
        for (int k = 0; k < E_; k++) {
            float di = I[k] - mi, dl = L[k] - ml;
            vi += di * di; vl += dl * dl;
        }
        vi *= 0.25f; vl *= 0.25f;
        float loss = 1e-2f * (vi / (mi * mi + 1e-10f) + vl / (ml * ml + 1e-10f));
        dout[NCHW_] = loss;
    }
}

// --------------------------------- launcher ---------------------------------
extern "C" void kernel_launch(void* const* d_in, const int* in_sizes, int n_in,
                              void* d_out, int out_size) {
    const float* x      = (const float*)d_in[0];
    const float* prompt = (const float*)d_in[1];
    const float* w_lin  = (const float*)d_in[2];
    const float* b_lin  = (const float*)d_in[3];
    const float* w_conv = (const float*)d_in[4];
    const float* w_gate = (const float*)d_in[5];
    const float* w1     = (const float*)d_in[6];
    const float* b1     = (const float*)d_in[7];
    const float* w2     = (const float*)d_in[8];
    const float* b2     = (const float*)d_in[9];
    float* out = (float*)d_out;

    cudaFuncSetAttribute(k_conv_gate, cudaFuncAttributeMaxDynamicSharedMemorySize, CV_BYTES);
    cudaFuncSetAttribute(k_expert, cudaFuncAttributeMaxDynamicSharedMemorySize, QX_BYTES);

    k_mean1<<<1024, 256>>>(x);
    k_prep<<<1, 256>>>(prompt, w_lin, b_lin, w_conv);
    k_scale1<<<9, 256>>>(w1, w2);
    k_scale2<<<1, 32>>>();
    k_packq<<<448, 256>>>(w1, w2);
    k_conv_gate<<<N_ / 64, 256, CV_BYTES>>>(x, w_gate);
    dim3 ge(N_ / 64, E_);
    k_expert<<<ge, 256, QX_BYTES>>>(b1, b2);
    k_combine<<<N_ / 64, 256>>>(x, out);
    k_loss<<<1, 128>>>(out, (out_size > NCHW_) ? 1 : 0);
}